// round 1
// baseline (speedup 1.0000x reference)
#include <cuda_runtime.h>
#include <cstdint>
#include <math_constants.h>

#define NSTEPS 512
#define KDIM   513
#define BATCH  65536
#define ROWS   511   // N-1
#define COLS   512   // K-1

// Static device scratch (allocation-free rule): ~6 MB total.
__device__ float        g_L[ROWS * COLS * 2];   // log-softmax table, 2 MB
__device__ float        g_logE[KDIM];           // log-softmax of endW
__device__ unsigned int g_xb[BATCH * 16];       // bit-packed x, 4 MB

// ---------------------------------------------------------------------------
// Kernel 1: L[s][j][c] = W[s][j][c] - logsumexp_c(W[s][j][:])
// ---------------------------------------------------------------------------
__global__ void prep_table(const float* __restrict__ W) {
    int idx = blockIdx.x * blockDim.x + threadIdx.x;
    if (idx < ROWS * COLS) {
        float w0 = W[idx * 2 + 0];
        float w1 = W[idx * 2 + 1];
        float m  = fmaxf(w0, w1);
        float lse = m + log1pf(expf(-fabsf(w0 - w1)));
        g_L[idx * 2 + 0] = w0 - lse;
        g_L[idx * 2 + 1] = w1 - lse;
    }
}

// ---------------------------------------------------------------------------
// Kernel 2: logE[k] = endW[k] - logsumexp(endW).  Single warp; tiny.
// ---------------------------------------------------------------------------
__global__ void prep_endw(const float* __restrict__ endW) {
    int lane = threadIdx.x;
    float m = -CUDART_INF_F;
    for (int k = lane; k < KDIM; k += 32) m = fmaxf(m, endW[k]);
    #pragma unroll
    for (int o = 16; o; o >>= 1) m = fmaxf(m, __shfl_xor_sync(0xffffffffu, m, o));
    float s = 0.f;
    for (int k = lane; k < KDIM; k += 32) s += expf(endW[k] - m);
    #pragma unroll
    for (int o = 16; o; o >>= 1) s += __shfl_xor_sync(0xffffffffu, s, o);
    float lse = m + logf(s);
    for (int k = lane; k < KDIM; k += 32) g_logE[k] = endW[k] - lse;
}

// ---------------------------------------------------------------------------
// Kernel 3: ballot-pack x (B,512) int32 -> (B,16) uint32, coalesced reads.
// word w of row b holds bits for steps [w*32, w*32+32), bit k = x[b, w*32+k].
// ---------------------------------------------------------------------------
__global__ void pack_x(const int* __restrict__ x) {
    int gw   = (blockIdx.x * blockDim.x + threadIdx.x) >> 5;   // global warp id
    int lane = threadIdx.x & 31;
    // gw in [0, BATCH*16)
    int b = gw >> 4;
    int w = gw & 15;
    int v = x[b * NSTEPS + w * 32 + lane];
    unsigned int word = __ballot_sync(0xffffffffu, v != 0);
    if (lane == 0) g_xb[gw] = word;
}

// ---------------------------------------------------------------------------
// Kernel 4: main walk. One batch row per thread.
//   p_t = prefix popcount; contribution L[t-1][p_t-1][x_t] when 1 <= p_t <= t.
// __syncthreads() per 32-step chunk keeps all warps of the block inside the
// same 128 KB table window so it stays L1-resident.
// ---------------------------------------------------------------------------
__global__ void __launch_bounds__(256) walk_kernel(float* __restrict__ out) {
    int b = blockIdx.x * 256 + threadIdx.x;
    const float* __restrict__ L = g_L;
    const unsigned int* __restrict__ xw = &g_xb[(size_t)b * 16];

    int   p   = 0;
    float acc = 0.f;

    #pragma unroll 1
    for (int w = 0; w < 16; ++w) {
        unsigned int word = xw[w];
        __syncthreads();   // keep warps in lockstep over the table window
        #pragma unroll
        for (int k = 0; k < 32; ++k) {
            int t   = w * 32 + k;
            int bit = (int)(word & 1u);
            word >>= 1;
            p += bit;
            // interior: 1 <= p <= t  (t==0 always skips; corners give log(1)=0)
            if ((p >= 1) & (p <= t)) {
                acc += __ldg(&L[(((t - 1) * COLS) + (p - 1)) * 2 + bit]);
            }
        }
    }
    acc += g_logE[p];
    out[b] = acc;
}

// ---------------------------------------------------------------------------
// Launch
// ---------------------------------------------------------------------------
extern "C" void kernel_launch(void* const* d_in, const int* in_sizes, int n_in,
                              void* d_out, int out_size) {
    const int*   x    = (const int*)  d_in[0];   // (65536, 512) int32
    const float* W    = (const float*)d_in[1];   // (511, 512, 2) float32
    const float* endW = (const float*)d_in[2];   // (1, 513) float32
    float* out = (float*)d_out;                  // (65536, 1) float32

    (void)in_sizes; (void)n_in; (void)out_size;

    // Table prep: 511*512 = 261632 pairs
    prep_table<<<(ROWS * COLS + 255) / 256, 256>>>(W);
    prep_endw<<<1, 32>>>(endW);

    // Pack: BATCH*16 words, one warp per word -> BATCH*16*32 threads
    {
        long long total_threads = (long long)BATCH * 16 * 32;
        int threads = 256;
        int blocks  = (int)(total_threads / threads);
        pack_x<<<blocks, threads>>>(x);
    }

    // Main walk: one thread per batch row
    walk_kernel<<<BATCH / 256, 256>>>(out);
}

// round 2
// speedup vs baseline: 2.3295x; 2.3295x over previous
#include <cuda_runtime.h>
#include <cstdint>
#include <math_constants.h>

#define NSTEPS 512
#define KDIM   513
#define BATCH  65536
#define ROWS   511   // N-1
#define COLS   512   // K-1
#define NSEG   4
#define SEGLEN 128   // steps per segment (4 words)

// Static device scratch (allocation-free rule): ~8 MB total.
__device__ float        g_L[ROWS * COLS * 2];       // log-softmax table, 2 MB
__device__ float        g_logE[KDIM];               // log-softmax of endW
__device__ unsigned int g_xb[BATCH * 16];           // bit-packed x, 4 MB
__device__ int          g_ps[BATCH * NSEG];         // prefix popcount at segment starts
__device__ float        g_part[NSEG * BATCH];       // per-segment partial sums

// ---------------------------------------------------------------------------
// Kernel 1: L[s][j][c] = W[s][j][c] - logsumexp_c(W[s][j][:])
// ---------------------------------------------------------------------------
__global__ void prep_table(const float* __restrict__ W) {
    int idx = blockIdx.x * blockDim.x + threadIdx.x;
    if (idx < ROWS * COLS) {
        float w0 = W[idx * 2 + 0];
        float w1 = W[idx * 2 + 1];
        float m  = fmaxf(w0, w1);
        float lse = m + log1pf(expf(-fabsf(w0 - w1)));
        g_L[idx * 2 + 0] = w0 - lse;
        g_L[idx * 2 + 1] = w1 - lse;
    }
}

// ---------------------------------------------------------------------------
// Kernel 2: logE[k] = endW[k] - logsumexp(endW).  Single warp; tiny.
// ---------------------------------------------------------------------------
__global__ void prep_endw(const float* __restrict__ endW) {
    int lane = threadIdx.x;
    float m = -CUDART_INF_F;
    for (int k = lane; k < KDIM; k += 32) m = fmaxf(m, endW[k]);
    #pragma unroll
    for (int o = 16; o; o >>= 1) m = fmaxf(m, __shfl_xor_sync(0xffffffffu, m, o));
    float s = 0.f;
    for (int k = lane; k < KDIM; k += 32) s += expf(endW[k] - m);
    #pragma unroll
    for (int o = 16; o; o >>= 1) s += __shfl_xor_sync(0xffffffffu, s, o);
    float lse = m + logf(s);
    for (int k = lane; k < KDIM; k += 32) g_logE[k] = endW[k] - lse;
}

// ---------------------------------------------------------------------------
// Kernel 3: pack x. One warp per batch row. int4 coalesced loads (2KB/row).
// Word w, bit k  <=>  x[row, w*32 + k].
// Also emits segment-start prefix popcounts g_ps[row*4 + seg].
// ---------------------------------------------------------------------------
__global__ void pack_x(const int* __restrict__ x) {
    int warp = (blockIdx.x * blockDim.x + threadIdx.x) >> 5;   // row id
    int lane = threadIdx.x & 31;
    const int4* __restrict__ xr = (const int4*)(x + (size_t)warp * NSTEPS);

    unsigned int words[NSEG];   // this lane's group word per iteration
    int sc[NSEG];               // popcount per 128-step segment (warp-uniform)

    #pragma unroll
    for (int it = 0; it < NSEG; ++it) {
        int4 v = xr[it * 32 + lane];   // steps it*128 + lane*4 .. +3
        unsigned int nib = (unsigned)(v.x != 0)
                         | ((unsigned)(v.y != 0) << 1)
                         | ((unsigned)(v.z != 0) << 2)
                         | ((unsigned)(v.w != 0) << 3);
        unsigned int part = nib << ((lane & 7) * 4);
        part |= __shfl_xor_sync(0xffffffffu, part, 1);
        part |= __shfl_xor_sync(0xffffffffu, part, 2);
        part |= __shfl_xor_sync(0xffffffffu, part, 4);
        words[it] = part;                                  // word it*4 + lane/8
        sc[it] = __reduce_add_sync(0xffffffffu, __popc(nib));
    }

    if ((lane & 7) == 0) {
        int g = lane >> 3;
        #pragma unroll
        for (int it = 0; it < NSEG; ++it)
            g_xb[warp * 16 + it * 4 + g] = words[it];
    }
    if (lane < NSEG) {
        int ps = 0;
        #pragma unroll
        for (int j = 0; j < NSEG; ++j) if (j < lane) ps += sc[j];
        g_ps[warp * NSEG + lane] = ps;
    }
}

// ---------------------------------------------------------------------------
// Kernel 4: segmented walk. Grid = NSEG*256 blocks; each block = 256 rows of
// ONE segment (warp lanes share t -> gather locality; block shares a 128-step
// table window -> L1 residency via per-word __syncthreads()).
// ---------------------------------------------------------------------------
__global__ void __launch_bounds__(256) walk_kernel() {
    int seg = blockIdx.x >> 8;                       // 256 blocks per segment
    int b   = ((blockIdx.x & 255) << 8) + threadIdx.x;

    const float* __restrict__ L = g_L;

    int p = g_ps[b * NSEG + seg];
    unsigned int w0 = g_xb[b * 16 + seg * 4 + 0];
    unsigned int w1 = g_xb[b * 16 + seg * 4 + 1];
    unsigned int w2 = g_xb[b * 16 + seg * 4 + 2];
    unsigned int w3 = g_xb[b * 16 + seg * 4 + 3];

    float acc = 0.f;
    int tbase = seg * SEGLEN;

    #pragma unroll 1
    for (int wi = 0; wi < 4; ++wi) {
        unsigned int word = (wi == 0) ? w0 : (wi == 1) ? w1 : (wi == 2) ? w2 : w3;
        __syncthreads();
        #pragma unroll
        for (int k = 0; k < 32; ++k) {
            int t   = tbase + wi * 32 + k;
            int bit = (int)(word & 1u);
            word >>= 1;
            p += bit;
            if ((p >= 1) & (p <= t)) {
                acc += __ldg(&L[(((t - 1) * COLS) + (p - 1)) * 2 + bit]);
            }
        }
    }

    if (seg == NSEG - 1) acc += g_logE[p];   // p here = total popcount
    g_part[seg * BATCH + b] = acc;           // coalesced
}

// ---------------------------------------------------------------------------
// Kernel 5: deterministic reduce of the 4 partials.
// ---------------------------------------------------------------------------
__global__ void reduce_kernel(float* __restrict__ out) {
    int b = blockIdx.x * blockDim.x + threadIdx.x;
    float s = g_part[b] + g_part[BATCH + b] + g_part[2 * BATCH + b]
            + g_part[3 * BATCH + b];
    out[b] = s;
}

// ---------------------------------------------------------------------------
// Launch
// ---------------------------------------------------------------------------
extern "C" void kernel_launch(void* const* d_in, const int* in_sizes, int n_in,
                              void* d_out, int out_size) {
    const int*   x    = (const int*)  d_in[0];   // (65536, 512) int32
    const float* W    = (const float*)d_in[1];   // (511, 512, 2) float32
    const float* endW = (const float*)d_in[2];   // (1, 513) float32
    float* out = (float*)d_out;                  // (65536, 1) float32

    (void)in_sizes; (void)n_in; (void)out_size;

    prep_table<<<(ROWS * COLS + 255) / 256, 256>>>(W);
    prep_endw<<<1, 32>>>(endW);

    // pack: one warp per row -> 65536 warps -> 8192 blocks of 256
    pack_x<<<(BATCH * 32) / 256, 256>>>(x);

    // walk: 4 segments x 256 blocks
    walk_kernel<<<NSEG * 256, 256>>>();

    reduce_kernel<<<BATCH / 256, 256>>>(out);
}

// round 3
// speedup vs baseline: 2.7788x; 1.1929x over previous
#include <cuda_runtime.h>
#include <cuda_fp16.h>
#include <cstdint>
#include <math_constants.h>

#define NSTEPS 512
#define KDIM   513
#define BATCH  65536
#define ROWS   511
#define COLS   512
#define NSEG   8          // 8 segments x 64 steps
#define NPAIR  256        // 2-step pairs over 512 steps

// Static device scratch: T2 2MB + xb 4MB + ps 2MB + part 2MB ≈ 10MB.
__device__ __half       g_T2[NPAIR * COLS * 4];  // fused 2-step log table (fp16)
__device__ float        g_logE[KDIM];
__device__ unsigned int g_xb[BATCH * 16];        // bit-packed x
__device__ int          g_ps[BATCH * NSEG];      // prefix popcount at segment starts
__device__ float        g_part[NSEG * BATCH];    // per-segment partials

// ---------------------------------------------------------------------------
// contrib(t, p_prev, b) = (1 <= p_prev+b <= t) ? logsoftmax(W[t-1][p_prev+b-1])[b] : 0
// ---------------------------------------------------------------------------
__device__ __forceinline__ float contrib(const float* __restrict__ W,
                                          int t, int pp, int b) {
    int pn = pp + b;
    if (pn < 1 || pn > t) return 0.f;
    int s = t - 1, j = pn - 1;
    float w0 = W[((size_t)s * COLS + j) * 2 + 0];
    float w1 = W[((size_t)s * COLS + j) * 2 + 1];
    float m  = fmaxf(w0, w1);
    float lse = m + log1pf(expf(-fabsf(w0 - w1)));
    return (b ? w1 : w0) - lse;
}

// Kernel 1: build fused 2-step table. T2[i][p][b0 + 2*b1] =
//   contrib(2i, p, b0) + contrib(2i+1, p+b0, b1), boundary zeros baked in.
__global__ void prep_T2(const float* __restrict__ W) {
    int idx = blockIdx.x * blockDim.x + threadIdx.x;   // [0, 256*512)
    int i = idx >> 9;
    int p = idx & (COLS - 1);
    int t0 = 2 * i, t1 = 2 * i + 1;
    float v[4];
    #pragma unroll
    for (int c = 0; c < 4; ++c) {
        int b0 = c & 1, b1 = c >> 1;
        v[c] = contrib(W, t0, p, b0) + contrib(W, t1, p + b0, b1);
    }
    __half2* dst = (__half2*)&g_T2[(size_t)idx * 4];
    dst[0] = __floats2half2_rn(v[0], v[1]);
    dst[1] = __floats2half2_rn(v[2], v[3]);
}

// Kernel 2: logE = logsoftmax(endW). Single warp.
__global__ void prep_endw(const float* __restrict__ endW) {
    int lane = threadIdx.x;
    float m = -CUDART_INF_F;
    for (int k = lane; k < KDIM; k += 32) m = fmaxf(m, endW[k]);
    #pragma unroll
    for (int o = 16; o; o >>= 1) m = fmaxf(m, __shfl_xor_sync(0xffffffffu, m, o));
    float s = 0.f;
    for (int k = lane; k < KDIM; k += 32) s += expf(endW[k] - m);
    #pragma unroll
    for (int o = 16; o; o >>= 1) s += __shfl_xor_sync(0xffffffffu, s, o);
    float lse = m + logf(s);
    for (int k = lane; k < KDIM; k += 32) g_logE[k] = endW[k] - lse;
}

// Kernel 3: pack x (one warp per row, int4 coalesced) + 8 segment-start
// prefix popcounts (64-step granularity).
__global__ void pack_x(const int* __restrict__ x) {
    int row  = (blockIdx.x * blockDim.x + threadIdx.x) >> 5;
    int lane = threadIdx.x & 31;
    const int4* __restrict__ xr = (const int4*)(x + (size_t)row * NSTEPS);
    const unsigned F = 0xffffffffu;

    unsigned int words[4];
    int hv[8];   // per-64-step popcounts (warp-uniform after broadcasts)

    #pragma unroll
    for (int it = 0; it < 4; ++it) {
        int4 v = xr[it * 32 + lane];            // steps it*128 + lane*4 ..+3
        unsigned int nib = (unsigned)(v.x != 0)
                         | ((unsigned)(v.y != 0) << 1)
                         | ((unsigned)(v.z != 0) << 2)
                         | ((unsigned)(v.w != 0) << 3);
        unsigned int part = nib << ((lane & 7) * 4);
        part |= __shfl_xor_sync(F, part, 1);
        part |= __shfl_xor_sync(F, part, 2);
        part |= __shfl_xor_sync(F, part, 4);
        words[it] = part;                        // word it*4 + lane/8

        int pc = __popc(nib);                    // half-warp sums (xor 1,2,4,8
        pc += __shfl_xor_sync(F, pc, 1);         //  mixes only within 16 lanes)
        pc += __shfl_xor_sync(F, pc, 2);
        pc += __shfl_xor_sync(F, pc, 4);
        pc += __shfl_xor_sync(F, pc, 8);
        hv[it * 2 + 0] = __shfl_sync(F, pc, 0);
        hv[it * 2 + 1] = __shfl_sync(F, pc, 16);
    }

    if ((lane & 7) == 0) {
        int g = lane >> 3;
        #pragma unroll
        for (int it = 0; it < 4; ++it)
            g_xb[row * 16 + it * 4 + g] = words[it];
    }
    if (lane < NSEG) {
        int ps = 0;
        #pragma unroll
        for (int j = 0; j < NSEG - 1; ++j) if (j < lane) ps += hv[j];
        g_ps[row * NSEG + lane] = ps;
    }
}

// Kernel 4: segmented walk, 2 steps per gather, boundary-free inner loop.
// Grid = 8 segs x 256 blocks; block = 256 rows of one 64-step segment.
__global__ void __launch_bounds__(256) walk_kernel() {
    int seg = blockIdx.x >> 8;
    int b   = ((blockIdx.x & 255) << 8) + threadIdx.x;

    int p = g_ps[b * NSEG + seg];
    uint2 ww = *(const uint2*)&g_xb[b * 16 + seg * 2];

    const __half* __restrict__ T = g_T2 + (size_t)(seg * 32) * (COLS * 4);
    float acc0 = 0.f, acc1 = 0.f;

    #pragma unroll 1
    for (int w = 0; w < 2; ++w) {
        unsigned int word = w ? ww.y : ww.x;
        const __half* __restrict__ Tw = T + (size_t)(w * 16) * (COLS * 4);
        __syncthreads();
        #pragma unroll
        for (int k = 0; k < 16; ++k) {
            int c = (int)(word & 3u);
            word >>= 2;
            float v = __half2float(__ldg(&Tw[k * (COLS * 4) + p * 4 + c]));
            if (k & 1) acc1 += v; else acc0 += v;
            p += __popc(c);
        }
    }

    float acc = acc0 + acc1;
    if (seg == NSEG - 1) acc += g_logE[p];
    g_part[seg * BATCH + b] = acc;
}

// Kernel 5: deterministic reduce of the 8 partials.
__global__ void reduce_kernel(float* __restrict__ out) {
    int b = blockIdx.x * blockDim.x + threadIdx.x;
    float s = 0.f;
    #pragma unroll
    for (int j = 0; j < NSEG; ++j) s += g_part[j * BATCH + b];
    out[b] = s;
}

// ---------------------------------------------------------------------------
extern "C" void kernel_launch(void* const* d_in, const int* in_sizes, int n_in,
                              void* d_out, int out_size) {
    const int*   x    = (const int*)  d_in[0];   // (65536, 512) int32
    const float* W    = (const float*)d_in[1];   // (511, 512, 2) float32
    const float* endW = (const float*)d_in[2];   // (1, 513) float32
    float* out = (float*)d_out;

    (void)in_sizes; (void)n_in; (void)out_size;

    prep_T2<<<(NPAIR * COLS) / 256, 256>>>(W);
    prep_endw<<<1, 32>>>(endW);
    pack_x<<<(BATCH * 32) / 256, 256>>>(x);
    walk_kernel<<<NSEG * 256, 256>>>();
    reduce_kernel<<<BATCH / 256, 256>>>(out);
}

// round 4
// speedup vs baseline: 3.2729x; 1.1778x over previous
#include <cuda_runtime.h>
#include <cuda_fp16.h>
#include <cstdint>
#include <math_constants.h>

#define NSTEPS 512
#define KDIM   513
#define BATCH  65536
#define ROWS   511
#define COLS   512
#define NSEG   8          // 8 segments x 64 steps
#define NPAIR  256        // 2-step pairs

#define PREP_BLOCKS 512   // 512*256 threads = 131072 = NPAIR*COLS
#define PACK_BLOCKS 8192  // 8192 blocks * 8 warps = 65536 rows

// Static device scratch: ~10 MB.
__device__ __half       g_T2[NPAIR * COLS * 4];  // fused 2-step log table (fp16)
__device__ float        g_logE[KDIM];
__device__ unsigned int g_xb[BATCH * 16];        // bit-packed x
__device__ int          g_ps[BATCH * NSEG];      // prefix popcount at segment starts
__device__ float        g_part[NSEG * BATCH];    // per-segment partials
__device__ int          g_cnt[256];              // row-group completion tickets

// ---------------------------------------------------------------------------
__device__ __forceinline__ float contrib(const float* __restrict__ W,
                                          int t, int pp, int b) {
    int pn = pp + b;
    if (pn < 1 || pn > t) return 0.f;
    int s = t - 1, j = pn - 1;
    float w0 = W[((size_t)s * COLS + j) * 2 + 0];
    float w1 = W[((size_t)s * COLS + j) * 2 + 1];
    float m  = fmaxf(w0, w1);
    float lse = m + log1pf(expf(-fabsf(w0 - w1)));
    return (b ? w1 : w0) - lse;
}

// ---------------------------------------------------------------------------
// Kernel 1: everything that reads the inputs, fused into one grid.
//   blk 0              : zero tickets + logsoftmax(endW)
//   blks [1, 513)      : build fused 2-step table T2
//   blks [513, 8705)   : bit-pack x + segment-start prefix popcounts
// Prep blocks are first so they are scheduled immediately and hide under the
// pack part's 134 MB DRAM stream.
// ---------------------------------------------------------------------------
__global__ void __launch_bounds__(256) fused_prep_pack(
        const int* __restrict__ x, const float* __restrict__ W,
        const float* __restrict__ endW) {
    int blk = blockIdx.x;
    int tid = threadIdx.x;

    if (blk == 0) {
        g_cnt[tid] = 0;
        if (tid < 32) {
            int lane = tid;
            float m = -CUDART_INF_F;
            for (int k = lane; k < KDIM; k += 32) m = fmaxf(m, endW[k]);
            #pragma unroll
            for (int o = 16; o; o >>= 1) m = fmaxf(m, __shfl_xor_sync(0xffffffffu, m, o));
            float s = 0.f;
            for (int k = lane; k < KDIM; k += 32) s += expf(endW[k] - m);
            #pragma unroll
            for (int o = 16; o; o >>= 1) s += __shfl_xor_sync(0xffffffffu, s, o);
            float lse = m + logf(s);
            for (int k = lane; k < KDIM; k += 32) g_logE[k] = endW[k] - lse;
        }
        return;
    }

    if (blk < 1 + PREP_BLOCKS) {
        int idx = (blk - 1) * 256 + tid;          // [0, NPAIR*COLS)
        int i = idx >> 9;
        int p = idx & (COLS - 1);
        int t0 = 2 * i, t1 = 2 * i + 1;
        float v[4];
        #pragma unroll
        for (int c = 0; c < 4; ++c) {
            int b0 = c & 1, b1 = c >> 1;
            v[c] = contrib(W, t0, p, b0) + contrib(W, t1, p + b0, b1);
        }
        __half2* dst = (__half2*)&g_T2[(size_t)idx * 4];
        dst[0] = __floats2half2_rn(v[0], v[1]);
        dst[1] = __floats2half2_rn(v[2], v[3]);
        return;
    }

    // ---- pack part: one warp per row ----
    int row  = (blk - 1 - PREP_BLOCKS) * 8 + (tid >> 5);
    int lane = tid & 31;
    const int4* __restrict__ xr = (const int4*)(x + (size_t)row * NSTEPS);
    const unsigned F = 0xffffffffu;

    unsigned int words[4];
    int hv[8];

    #pragma unroll
    for (int it = 0; it < 4; ++it) {
        int4 v = xr[it * 32 + lane];
        unsigned int nib = (unsigned)(v.x != 0)
                         | ((unsigned)(v.y != 0) << 1)
                         | ((unsigned)(v.z != 0) << 2)
                         | ((unsigned)(v.w != 0) << 3);
        unsigned int part = nib << ((lane & 7) * 4);
        part |= __shfl_xor_sync(F, part, 1);
        part |= __shfl_xor_sync(F, part, 2);
        part |= __shfl_xor_sync(F, part, 4);
        words[it] = part;

        int pc = __popc(nib);                  // xor 1,2,4,8 stays within 16 lanes
        pc += __shfl_xor_sync(F, pc, 1);
        pc += __shfl_xor_sync(F, pc, 2);
        pc += __shfl_xor_sync(F, pc, 4);
        pc += __shfl_xor_sync(F, pc, 8);
        hv[it * 2 + 0] = __shfl_sync(F, pc, 0);
        hv[it * 2 + 1] = __shfl_sync(F, pc, 16);
    }

    if ((lane & 7) == 0) {
        int g = lane >> 3;
        #pragma unroll
        for (int it = 0; it < 4; ++it)
            g_xb[row * 16 + it * 4 + g] = words[it];
    }
    if (lane < NSEG) {
        int ps = 0;
        #pragma unroll
        for (int j = 0; j < NSEG - 1; ++j) if (j < lane) ps += hv[j];
        g_ps[row * NSEG + lane] = ps;
    }
}

// ---------------------------------------------------------------------------
// Kernel 2: segmented walk + deterministic last-block reduction.
// Grid = 8 segs x 256 row-groups; block = 256 rows of one 64-step segment.
// ---------------------------------------------------------------------------
__global__ void __launch_bounds__(256) walk_kernel(float* __restrict__ out) {
    int seg = blockIdx.x >> 8;
    int grp = blockIdx.x & 255;
    int b   = (grp << 8) + threadIdx.x;

    int p = __ldg(&g_ps[b * NSEG + seg]);
    uint2 ww = *(const uint2*)&g_xb[b * 16 + seg * 2];

    const __half* __restrict__ T = g_T2 + (size_t)(seg * 32) * 2048;
    unsigned hq = (unsigned)p << 2;            // running half-index, multiple of 4
    float acc0 = 0.f, acc1 = 0.f;

    #pragma unroll 1
    for (int w = 0; w < 2; ++w) {
        unsigned int word = w ? ww.y : ww.x;
        const __half* __restrict__ Tw = T + (size_t)(w * 16) * 2048;
        __syncthreads();                       // keep block in one table window
        #pragma unroll
        for (int k = 0; k < 16; ++k) {
            unsigned c = word & 3u;
            word >>= 2;
            float v = __half2float(__ldg(&Tw[k * 2048 + (hq | c)]));
            if (k & 1) acc1 += v; else acc0 += v;
            hq += (unsigned)__popc(c) << 2;
        }
    }

    float acc = acc0 + acc1;
    if (seg == NSEG - 1) acc += g_logE[hq >> 2];
    g_part[seg * BATCH + b] = acc;

    // --- last block of this row-group reduces all 8 segments ---
    __threadfence();
    __shared__ int ticket;
    if (threadIdx.x == 0) ticket = atomicAdd(&g_cnt[grp], 1);
    __syncthreads();
    if (ticket == NSEG - 1) {
        __threadfence();
        float s = 0.f;
        #pragma unroll
        for (int j = 0; j < NSEG; ++j) s += g_part[j * BATCH + b];
        out[b] = s;
    }
}

// ---------------------------------------------------------------------------
extern "C" void kernel_launch(void* const* d_in, const int* in_sizes, int n_in,
                              void* d_out, int out_size) {
    const int*   x    = (const int*)  d_in[0];   // (65536, 512) int32
    const float* W    = (const float*)d_in[1];   // (511, 512, 2) float32
    const float* endW = (const float*)d_in[2];   // (1, 513) float32
    float* out = (float*)d_out;

    (void)in_sizes; (void)n_in; (void)out_size;

    fused_prep_pack<<<1 + PREP_BLOCKS + PACK_BLOCKS, 256>>>(x, W, endW);
    walk_kernel<<<NSEG * 256, 256>>>(out);
}

// round 5
// speedup vs baseline: 3.3186x; 1.0140x over previous
#include <cuda_runtime.h>
#include <cuda_fp16.h>
#include <cstdint>
#include <math_constants.h>

#define NSTEPS 512
#define KDIM   513
#define BATCH  65536
#define ROWS   511
#define COLS   512
#define NSEG   8          // 8 segments x 64 steps
#define NPAIR  256        // 2-step pairs
#define RPB    32         // rows per block in the mega kernel

#define PREP_BLOCKS 512   // 512*256 = 131072 = NPAIR*COLS table entries

// Persistent tables only (~2 MB).
__device__ __half g_T2[NPAIR * COLS * 4];   // fused 2-step log table (fp16)
__device__ float  g_logE[KDIM];

// ---------------------------------------------------------------------------
// contrib(t, p_prev, b) = (1 <= p_prev+b <= t) ? logsoftmax(W[t-1][p_prev+b-1])[b] : 0
// ---------------------------------------------------------------------------
__device__ __forceinline__ float contrib(const float* __restrict__ W,
                                          int t, int pp, int b) {
    int pn = pp + b;
    if (pn < 1 || pn > t) return 0.f;
    int s = t - 1, j = pn - 1;
    float w0 = W[((size_t)s * COLS + j) * 2 + 0];
    float w1 = W[((size_t)s * COLS + j) * 2 + 1];
    float m  = fmaxf(w0, w1);
    float lse = m + log1pf(expf(-fabsf(w0 - w1)));
    return (b ? w1 : w0) - lse;
}

// ---------------------------------------------------------------------------
// Kernel 1: build T2 (blocks [0,512)) + logsoftmax(endW) (block 512).
// ---------------------------------------------------------------------------
__global__ void __launch_bounds__(256) prep_kernel(
        const float* __restrict__ W, const float* __restrict__ endW) {
    int blk = blockIdx.x;
    if (blk == PREP_BLOCKS) {
        if (threadIdx.x < 32) {
            int lane = threadIdx.x;
            float m = -CUDART_INF_F;
            for (int k = lane; k < KDIM; k += 32) m = fmaxf(m, endW[k]);
            #pragma unroll
            for (int o = 16; o; o >>= 1) m = fmaxf(m, __shfl_xor_sync(0xffffffffu, m, o));
            float s = 0.f;
            for (int k = lane; k < KDIM; k += 32) s += expf(endW[k] - m);
            #pragma unroll
            for (int o = 16; o; o >>= 1) s += __shfl_xor_sync(0xffffffffu, s, o);
            float lse = m + logf(s);
            for (int k = lane; k < KDIM; k += 32) g_logE[k] = endW[k] - lse;
        }
        return;
    }
    int idx = blk * 256 + threadIdx.x;            // [0, NPAIR*COLS)
    int i = idx >> 9;
    int p = idx & (COLS - 1);
    int t0 = 2 * i, t1 = 2 * i + 1;
    float v[4];
    #pragma unroll
    for (int c = 0; c < 4; ++c) {
        int b0 = c & 1, b1 = c >> 1;
        v[c] = contrib(W, t0, p, b0) + contrib(W, t1, p + b0, b1);
    }
    __half2* dst = (__half2*)&g_T2[(size_t)idx * 4];
    dst[0] = __floats2half2_rn(v[0], v[1]);
    dst[1] = __floats2half2_rn(v[2], v[3]);
}

// ---------------------------------------------------------------------------
// Kernel 2: mega kernel. Block = 32 rows, 256 threads.
//   Phase 1: warp w packs rows [w*4, w*4+4) of the block (coalesced int4) into
//            smem words + per-segment prefix popcounts.
//   Phase 2: thread (warp=seg, lane=row) walks its 64-step segment; warp lanes
//            are 32 rows at identical t -> tight gather locality.
//   Phase 3: fixed-order smem reduce, warp 0 writes 32 outputs.
// No global scratch, no atomics.
// ---------------------------------------------------------------------------
__global__ void __launch_bounds__(256) mega_kernel(
        const int* __restrict__ x, float* __restrict__ out) {
    __shared__ unsigned int s_words[RPB][17];   // 16 words + pad
    __shared__ int          s_ps[RPB][9];       // 8 prefixes + pad
    __shared__ float        s_part[NSEG][RPB];

    const unsigned F = 0xffffffffu;
    int w    = threadIdx.x >> 5;                // warp id
    int lane = threadIdx.x & 31;
    int r0   = blockIdx.x * RPB;

    // ---- Phase 1: pack 4 rows per warp ----
    #pragma unroll 1
    for (int i = 0; i < 4; ++i) {
        int row_local = w * 4 + i;
        const int4* __restrict__ xr =
            (const int4*)(x + (size_t)(r0 + row_local) * NSTEPS);

        unsigned int words[4];
        int hv[8];
        #pragma unroll
        for (int it = 0; it < 4; ++it) {
            int4 v = xr[it * 32 + lane];        // steps it*128 + lane*4 ..+3
            unsigned int nib = (unsigned)(v.x != 0)
                             | ((unsigned)(v.y != 0) << 1)
                             | ((unsigned)(v.z != 0) << 2)
                             | ((unsigned)(v.w != 0) << 3);
            unsigned int part = nib << ((lane & 7) * 4);
            part |= __shfl_xor_sync(F, part, 1);
            part |= __shfl_xor_sync(F, part, 2);
            part |= __shfl_xor_sync(F, part, 4);
            words[it] = part;                   // word it*4 + lane/8

            int pc = __popc(nib);               // xor 1,2,4,8 stays in 16 lanes
            pc += __shfl_xor_sync(F, pc, 1);
            pc += __shfl_xor_sync(F, pc, 2);
            pc += __shfl_xor_sync(F, pc, 4);
            pc += __shfl_xor_sync(F, pc, 8);
            hv[it * 2 + 0] = __shfl_sync(F, pc, 0);
            hv[it * 2 + 1] = __shfl_sync(F, pc, 16);
        }
        if ((lane & 7) == 0) {
            int g = lane >> 3;
            #pragma unroll
            for (int it = 0; it < 4; ++it)
                s_words[row_local][it * 4 + g] = words[it];
        }
        if (lane < NSEG) {
            int ps = 0;
            #pragma unroll
            for (int j = 0; j < NSEG - 1; ++j) if (j < lane) ps += hv[j];
            s_ps[row_local][lane] = ps;
        }
    }
    __syncthreads();

    // ---- Phase 2: walk. seg = w, row = lane ----
    int p = s_ps[lane][w];
    unsigned int wd0 = s_words[lane][2 * w + 0];
    unsigned int wd1 = s_words[lane][2 * w + 1];

    const __half* __restrict__ T = g_T2 + (size_t)(w * 32) * 2048;
    unsigned hq = (unsigned)p << 2;             // running half-index, mult of 4
    float acc0 = 0.f, acc1 = 0.f;

    #pragma unroll 1
    for (int half = 0; half < 2; ++half) {
        unsigned int word = half ? wd1 : wd0;
        const __half* __restrict__ Tw = T + (size_t)(half * 16) * 2048;
        #pragma unroll
        for (int k = 0; k < 16; ++k) {
            unsigned c = word & 3u;
            word >>= 2;
            float v = __half2float(__ldg(&Tw[k * 2048 + (hq | c)]));
            if (k & 1) acc1 += v; else acc0 += v;
            hq += (unsigned)__popc(c) << 2;
        }
    }

    float acc = acc0 + acc1;
    if (w == NSEG - 1) acc += g_logE[hq >> 2];  // hq/4 = total popcount
    s_part[w][lane] = acc;
    __syncthreads();

    // ---- Phase 3: fixed-order reduce, warp 0 writes ----
    if (w == 0) {
        float s = 0.f;
        #pragma unroll
        for (int j = 0; j < NSEG; ++j) s += s_part[j][lane];
        out[r0 + lane] = s;
    }
}

// ---------------------------------------------------------------------------
extern "C" void kernel_launch(void* const* d_in, const int* in_sizes, int n_in,
                              void* d_out, int out_size) {
    const int*   x    = (const int*)  d_in[0];   // (65536, 512) int32
    const float* W    = (const float*)d_in[1];   // (511, 512, 2) float32
    const float* endW = (const float*)d_in[2];   // (1, 513) float32
    float* out = (float*)d_out;

    (void)in_sizes; (void)n_in; (void)out_size;

    prep_kernel<<<PREP_BLOCKS + 1, 256>>>(W, endW);
    mega_kernel<<<BATCH / RPB, 256>>>(x, out);
}

// round 7
// speedup vs baseline: 3.3532x; 1.0104x over previous
#include <cuda_runtime.h>
#include <cuda_fp16.h>
#include <cstdint>
#include <math_constants.h>

#define NSTEPS 512
#define KDIM   513
#define BATCH  65536
#define COLS   512
#define NSEG   8           // 8 segments x 64 steps
#define NQUAD  128         // 4-step quads
#define RPB    32          // rows per mega block

#define PREP_BLOCKS 256    // 128 i-slices x 2 p-chunks

// Persistent tables (~2 MB).
__device__ __half g_T4[NQUAD * COLS * 16];  // fused 4-step log table (fp16)
__device__ float  g_logE[KDIM];

// ---------------------------------------------------------------------------
// Kernel 1: build T4. Block = one (i, 256-wide p-chunk): compute the 4x260
// log-softmax window ONCE into smem, then combine 16 bit-combos per thread.
// T4[i][p][c] = sum_{k=0..3} [1 <= q_k <= 4i+k] * LS[4i+k-1][q_k-1][b_k],
//   b_k = bit k of c, q_k = p + popc(c & ((1<<(k+1))-1)).
// Block PREP_BLOCKS does logsoftmax(endW).
// ---------------------------------------------------------------------------
__global__ void __launch_bounds__(256) prep_kernel(
        const float* __restrict__ W, const float* __restrict__ endW) {
    if (blockIdx.x == PREP_BLOCKS) {
        if (threadIdx.x < 32) {
            int lane = threadIdx.x;
            float m = -CUDART_INF_F;
            for (int k = lane; k < KDIM; k += 32) m = fmaxf(m, endW[k]);
            #pragma unroll
            for (int o = 16; o; o >>= 1) m = fmaxf(m, __shfl_xor_sync(0xffffffffu, m, o));
            float s = 0.f;
            for (int k = lane; k < KDIM; k += 32) s += __expf(endW[k] - m);
            #pragma unroll
            for (int o = 16; o; o >>= 1) s += __shfl_xor_sync(0xffffffffu, s, o);
            float lse = m + __logf(s);
            for (int k = lane; k < KDIM; k += 32) g_logE[k] = endW[k] - lse;
        }
        return;
    }

    int i     = blockIdx.x >> 1;
    int pbase = (blockIdx.x & 1) << 8;

    // ls[k][jj][b]: log-softmax for step t=4i+k at j = pbase-1+jj.
    __shared__ float ls[4][260][2];

    for (int idx = threadIdx.x; idx < 4 * 260; idx += 256) {
        int k  = idx / 260;
        int jj = idx - k * 260;
        int t  = 4 * i + k;
        int j  = pbase - 1 + jj;
        float l0 = 0.f, l1 = 0.f;
        if (j >= 0 && j <= t - 1) {
            float w0 = W[((size_t)(t - 1) * COLS + j) * 2 + 0];
            float w1 = W[((size_t)(t - 1) * COLS + j) * 2 + 1];
            float m  = fmaxf(w0, w1);
            float lse = m + __logf(1.f + __expf(-fabsf(w0 - w1)));
            l0 = w0 - lse;
            l1 = w1 - lse;
        }
        ls[k][jj][0] = l0;
        ls[k][jj][1] = l1;
    }
    __syncthreads();

    int p = pbase + threadIdx.x;
    __align__(16) __half2 hv[8];
    #pragma unroll
    for (int cp = 0; cp < 8; ++cp) {
        float v2[2];
        #pragma unroll
        for (int lo = 0; lo < 2; ++lo) {
            int c = cp * 2 + lo;
            int q = p;
            float v = 0.f;
            #pragma unroll
            for (int k = 0; k < 4; ++k) {
                int b  = (c >> k) & 1;
                int qn = q + b;
                int t  = 4 * i + k;
                if (qn >= 1 && qn <= t) v += ls[k][qn - pbase][b];
                q = qn;
            }
            v2[lo] = v;
        }
        hv[cp] = __floats2half2_rn(v2[0], v2[1]);
    }
    // 16 halves = 32 B contiguous per thread -> 2x STG.128, fully coalesced.
    const uint4* src = reinterpret_cast<const uint4*>(hv);
    uint4* dst = reinterpret_cast<uint4*>(&g_T4[((size_t)i * COLS + p) * 16]);
    dst[0] = src[0];
    dst[1] = src[1];
}

// ---------------------------------------------------------------------------
// Kernel 2: mega kernel. Block = 32 rows, 256 threads.
//   Phase 1: warp w packs rows [w*4,w*4+4) (coalesced int4) -> smem bits +
//            per-64-step prefix popcounts.
//   Phase 2: thread (warp=seg, lane=row) walks 64 steps = 16 quad-gathers.
//   Phase 3: fixed-order reduce, warp 0 writes.
// ---------------------------------------------------------------------------
__global__ void __launch_bounds__(256) mega_kernel(
        const int* __restrict__ x, float* __restrict__ out) {
    __shared__ unsigned int s_words[RPB][17];
    __shared__ int          s_ps[RPB][9];
    __shared__ float        s_part[NSEG][RPB];

    const unsigned F = 0xffffffffu;
    int w    = threadIdx.x >> 5;
    int lane = threadIdx.x & 31;
    int r0   = blockIdx.x * RPB;

    // ---- Phase 1: pack ----
    #pragma unroll 1
    for (int i = 0; i < 4; ++i) {
        int row_local = w * 4 + i;
        const int4* __restrict__ xr =
            (const int4*)(x + (size_t)(r0 + row_local) * NSTEPS);

        unsigned int words[4];
        int hv[8];
        #pragma unroll
        for (int it = 0; it < 4; ++it) {
            int4 v = xr[it * 32 + lane];
            unsigned int nib = (unsigned)(v.x != 0)
                             | ((unsigned)(v.y != 0) << 1)
                             | ((unsigned)(v.z != 0) << 2)
                             | ((unsigned)(v.w != 0) << 3);
            unsigned int part = nib << ((lane & 7) * 4);
            part |= __shfl_xor_sync(F, part, 1);
            part |= __shfl_xor_sync(F, part, 2);
            part |= __shfl_xor_sync(F, part, 4);
            words[it] = part;

            int pc = __popc(nib);            // xor 1,2,4,8 stays in 16 lanes
            pc += __shfl_xor_sync(F, pc, 1);
            pc += __shfl_xor_sync(F, pc, 2);
            pc += __shfl_xor_sync(F, pc, 4);
            pc += __shfl_xor_sync(F, pc, 8);
            hv[it * 2 + 0] = __shfl_sync(F, pc, 0);
            hv[it * 2 + 1] = __shfl_sync(F, pc, 16);
        }
        if ((lane & 7) == 0) {
            int g = lane >> 3;
            #pragma unroll
            for (int it = 0; it < 4; ++it)
                s_words[row_local][it * 4 + g] = words[it];
        }
        if (lane < NSEG) {
            int ps = 0;
            #pragma unroll
            for (int j = 0; j < NSEG - 1; ++j) if (j < lane) ps += hv[j];
            s_ps[row_local][lane] = ps;
        }
    }
    __syncthreads();

    // ---- Phase 2: walk. seg = w, row = lane. 16 quad-gathers. ----
    int p = s_ps[lane][w];
    unsigned int wd0 = s_words[lane][2 * w + 0];
    unsigned int wd1 = s_words[lane][2 * w + 1];

    const __half* __restrict__ T = g_T4 + (size_t)(w * 16) * 8192;
    unsigned hq = (unsigned)p << 4;          // running index, multiple of 16
    float acc0 = 0.f, acc1 = 0.f;

    #pragma unroll 1
    for (int half = 0; half < 2; ++half) {
        unsigned int word = half ? wd1 : wd0;
        const __half* __restrict__ Tw = T + (size_t)(half * 8) * 8192;
        #pragma unroll
        for (int k = 0; k < 8; ++k) {
            unsigned c = word & 15u;
            word >>= 4;
            float v = __half2float(__ldg(&Tw[k * 8192 + (hq | c)]));
            if (k & 1) acc1 += v; else acc0 += v;
            hq += (unsigned)__popc(c) << 4;
        }
    }

    float acc = acc0 + acc1;
    if (w == NSEG - 1) acc += g_logE[hq >> 4];   // total popcount
    s_part[w][lane] = acc;
    __syncthreads();

    // ---- Phase 3: fixed-order reduce ----
    if (w == 0) {
        float s = 0.f;
        #pragma unroll
        for (int j = 0; j < NSEG; ++j) s += s_part[j][lane];
        out[r0 + lane] = s;
    }
}

// ---------------------------------------------------------------------------
extern "C" void kernel_launch(void* const* d_in, const int* in_sizes, int n_in,
                              void* d_out, int out_size) {
    const int*   x    = (const int*)  d_in[0];   // (65536, 512) int32
    const float* W    = (const float*)d_in[1];   // (511, 512, 2) float32
    const float* endW = (const float*)d_in[2];   // (1, 513) float32
    float* out = (float*)d_out;

    (void)in_sizes; (void)n_in; (void)out_size;

    prep_kernel<<<PREP_BLOCKS + 1, 256>>>(W, endW);
    mega_kernel<<<BATCH / RPB, 256>>>(x, out);
}